// round 5
// baseline (speedup 1.0000x reference)
#include <cuda_runtime.h>
#include <math.h>

#define BB 4
#define NN 65536
#define KK 16
#define HH 64
#define TPB 256

// Scratch: xyz repacked as float4 per point (w unused). 4*65536*16B = 4 MB.
__device__ float4 g_xyz4[BB * NN];
__device__ int g_idx_is64;

// Transpose pos (B,3,N) -> g_xyz4[b*N+n] = {x,y,z,0}, coalesced per coord.
// Warp 0 of block 0 also detects idx dtype: for int64 values < 65536 every odd
// 32-bit word is zero; for int32 those words are random indices.
__global__ void transpose_pos_kernel(const float* __restrict__ pos,
                                     const unsigned* __restrict__ idxw) {
    if (blockIdx.x == 0 && threadIdx.x < 32) {
        unsigned v = idxw[4 * threadIdx.x + 1] | idxw[4 * threadIdx.x + 3];
        unsigned any = __ballot_sync(0xffffffffu, v != 0u);
        if (threadIdx.x == 0) g_idx_is64 = (any == 0u) ? 1 : 0;
    }
    int t = blockIdx.x * blockDim.x + threadIdx.x;
    if (t >= BB * NN) return;
    int b = t >> 16;
    int n = t & (NN - 1);
    const float* p = pos + (size_t)b * 3 * NN;
    float4 v;
    v.x = p[n];
    v.y = p[NN + n];
    v.z = p[2 * NN + n];
    v.w = 0.0f;
    g_xyz4[t] = v;
}

__global__ __launch_bounds__(TPB, 4) void point_embed_kernel(
    const void* __restrict__ idxv,
    const float* __restrict__ dist,
    const float* __restrict__ W,
    const float* __restrict__ bias,
    float* __restrict__ out)
{
    __shared__ float feat_s[TPB][10];
    __shared__ float4 Ws[10][16];   // W[10][64] as float4 columns
    __shared__ float4 Bs[16];

    int tid = threadIdx.x;
    for (int i = tid; i < 160; i += TPB)
        Ws[i >> 4][i & 15] = ((const float4*)W)[i];
    if (tid < 16) Bs[tid] = ((const float4*)bias)[tid];

    int t = blockIdx.x * TPB + tid;   // this thread's point (phase 1)
    int base = (t >> 16) << 16;       // batch base

    float4 p = g_xyz4[t];

    float mnx = -INFINITY, mny = -INFINITY, mnz = -INFINITY;
    float mdx = -INFINITY, mdy = -INFINITY, mdz = -INFINITY;

    // ---- gathers in two batches of 8 (bounds register pressure, MLP=8) ----
    bool is64 = (g_idx_is64 != 0);
#pragma unroll
    for (int h = 0; h < 2; h++) {
        int id[8];
        if (is64) {
            const int4* q = (const int4*)((const char*)idxv + (size_t)t * (KK * 8)) + h * 4;
#pragma unroll
            for (int i = 0; i < 4; i++) {
                int4 v = q[i];
                id[2 * i + 0] = v.x & (NN - 1);
                id[2 * i + 1] = v.z & (NN - 1);
            }
        } else {
            const int4* q = (const int4*)((const char*)idxv + (size_t)t * (KK * 4)) + h * 2;
#pragma unroll
            for (int i = 0; i < 2; i++) {
                int4 v = q[i];
                id[4 * i + 0] = v.x & (NN - 1);
                id[4 * i + 1] = v.y & (NN - 1);
                id[4 * i + 2] = v.z & (NN - 1);
                id[4 * i + 3] = v.w & (NN - 1);
            }
        }
#pragma unroll
        for (int k = 0; k < 8; k++) {
            float4 q = g_xyz4[base + id[k]];   // one LDG.128, L2-resident
            mnx = fmaxf(mnx, q.x);
            mny = fmaxf(mny, q.y);
            mnz = fmaxf(mnz, q.z);
            mdx = fmaxf(mdx, p.x - q.x);
            mdy = fmaxf(mdy, p.y - q.y);
            mdz = fmaxf(mdz, p.z - q.z);
        }
    }

    // ---- dist max, reduced as loaded (2 float4 live) ----
    const float4* d4 = (const float4*)(dist + (size_t)t * KK);
    float4 da = d4[0], db = d4[1];
    da.x = fmaxf(fmaxf(da.x, da.y), fmaxf(da.z, da.w));
    db.x = fmaxf(fmaxf(db.x, db.y), fmaxf(db.z, db.w));
    float md = fmaxf(da.x, db.x);
    da = d4[2]; db = d4[3];
    da.x = fmaxf(fmaxf(da.x, da.y), fmaxf(da.z, da.w));
    db.x = fmaxf(fmaxf(db.x, db.y), fmaxf(db.z, db.w));
    md = fmaxf(md, fmaxf(da.x, db.x));

    feat_s[tid][0] = p.x;  feat_s[tid][1] = p.y;  feat_s[tid][2] = p.z;
    feat_s[tid][3] = mnx;  feat_s[tid][4] = mny;  feat_s[tid][5] = mnz;
    feat_s[tid][6] = mdx;  feat_s[tid][7] = mdy;  feat_s[tid][8] = mdz;
    feat_s[tid][9] = md;

    __syncthreads();

    // ---- Phase 2: matvec + relu, coalesced stores ----
    // Lanes 0-15 of each half-warp handle one point's 64 channels:
    // each warp stores 512B contiguous (4 L1 wavefronts).
    int c = tid & 15;          // fixed channel group (256 % 16 == 0)
    int sub = tid >> 4;        // 0..15
    long blk_base = (long)blockIdx.x * TPB;
#pragma unroll
    for (int it = 0; it < 16; it++) {
        int pl = it * 16 + sub;
        float4 acc = Bs[c];
#pragma unroll
        for (int j = 0; j < 10; j++) {
            float f = feat_s[pl][j];   // 2-addr broadcast LDS
            float4 w = Ws[j][c];       // LDS.128, 2-phase
            acc.x = fmaf(f, w.x, acc.x);
            acc.y = fmaf(f, w.y, acc.y);
            acc.z = fmaf(f, w.z, acc.z);
            acc.w = fmaf(f, w.w, acc.w);
        }
        acc.x = fmaxf(acc.x, 0.0f);
        acc.y = fmaxf(acc.y, 0.0f);
        acc.z = fmaxf(acc.z, 0.0f);
        acc.w = fmaxf(acc.w, 0.0f);
        ((float4*)(out + (blk_base + pl) * HH))[c] = acc;
    }
}

extern "C" void kernel_launch(void* const* d_in, const int* in_sizes, int n_in,
                              void* d_out, int out_size) {
    const float* pos  = (const float*)d_in[0];
    const void*  idx  = d_in[1];
    const float* dist = (const float*)d_in[2];
    const float* W    = (const float*)d_in[3];
    const float* bias = (const float*)d_in[4];
    float* out = (float*)d_out;

    transpose_pos_kernel<<<(BB * NN + TPB - 1) / TPB, TPB>>>(pos, (const unsigned*)idx);
    point_embed_kernel<<<(BB * NN) / TPB, TPB>>>(idx, dist, W, bias, out);
}

// round 10
// speedup vs baseline: 1.2244x; 1.2244x over previous
#include <cuda_runtime.h>
#include <math.h>

#define BB 4
#define NN 65536
#define KK 16
#define HH 64
#define TPB 256

// Scratch: xyz repacked as float4 per point (w unused). 4*65536*16B = 4 MB.
__device__ float4 g_xyz4[BB * NN];
__device__ int g_idx_is64;

// Transpose pos (B,3,N) -> g_xyz4[b*N+n] = {x,y,z,0}, coalesced per coord.
// Warp 0 of block 0 also detects idx dtype: for int64 values < 65536 every odd
// 32-bit word is zero; for int32 those words are random indices.
__global__ void transpose_pos_kernel(const float* __restrict__ pos,
                                     const unsigned* __restrict__ idxw) {
    if (blockIdx.x == 0 && threadIdx.x < 32) {
        unsigned v = idxw[4 * threadIdx.x + 1] | idxw[4 * threadIdx.x + 3];
        unsigned any = __ballot_sync(0xffffffffu, v != 0u);
        if (threadIdx.x == 0) g_idx_is64 = (any == 0u) ? 1 : 0;
    }
    int t = blockIdx.x * blockDim.x + threadIdx.x;
    if (t >= BB * NN) return;
    int b = t >> 16;
    int n = t & (NN - 1);
    const float* p = pos + (size_t)b * 3 * NN;
    float4 v;
    v.x = p[n];
    v.y = p[NN + n];
    v.z = p[2 * NN + n];
    v.w = 0.0f;
    g_xyz4[t] = v;
}

__global__ __launch_bounds__(TPB, 3) void point_embed_kernel(
    const void* __restrict__ idxv,
    const float* __restrict__ dist,
    const float* __restrict__ W,
    const float* __restrict__ bias,
    float* __restrict__ out)
{
    __shared__ float feat_s[TPB][10];
    __shared__ float4 Ws[10][16];   // W[10][64] as float4 columns
    __shared__ float4 Bs[16];

    int tid = threadIdx.x;
    for (int i = tid; i < 160; i += TPB)
        Ws[i >> 4][i & 15] = ((const float4*)W)[i];
    if (tid < 16) Bs[tid] = ((const float4*)bias)[tid];

    int t = blockIdx.x * TPB + tid;   // this thread's point (phase 1)
    int base = (t >> 16) << 16;       // batch base

    // ---- all 16 neighbor indices upfront (dtype-adaptive), MLP=16 gathers ----
    int id[KK];
    if (g_idx_is64 != 0) {
        const int4* q = (const int4*)((const char*)idxv + (size_t)t * (KK * 8));
#pragma unroll
        for (int i = 0; i < 8; i++) {
            int4 v = q[i];
            id[2 * i + 0] = v.x & (NN - 1);
            id[2 * i + 1] = v.z & (NN - 1);
        }
    } else {
        const int4* q = (const int4*)((const char*)idxv + (size_t)t * (KK * 4));
#pragma unroll
        for (int i = 0; i < 4; i++) {
            int4 v = q[i];
            id[4 * i + 0] = v.x & (NN - 1);
            id[4 * i + 1] = v.y & (NN - 1);
            id[4 * i + 2] = v.z & (NN - 1);
            id[4 * i + 3] = v.w & (NN - 1);
        }
    }

    float4 p = g_xyz4[t];

    float mnx = -INFINITY, mny = -INFINITY, mnz = -INFINITY;
    float mdx = -INFINITY, mdy = -INFINITY, mdz = -INFINITY;
#pragma unroll
    for (int k = 0; k < KK; k++) {
        float4 q = g_xyz4[base + id[k]];  // one LDG.128 per neighbor, L2-resident
        mnx = fmaxf(mnx, q.x);
        mny = fmaxf(mny, q.y);
        mnz = fmaxf(mnz, q.z);
        mdx = fmaxf(mdx, p.x - q.x);
        mdy = fmaxf(mdy, p.y - q.y);
        mdz = fmaxf(mdz, p.z - q.z);
    }

    // ---- dist max ----
    const float4* d4 = (const float4*)(dist + (size_t)t * KK);
    float4 da = d4[0], db = d4[1];
    float m0 = fmaxf(fmaxf(da.x, da.y), fmaxf(da.z, da.w));
    float m1 = fmaxf(fmaxf(db.x, db.y), fmaxf(db.z, db.w));
    da = d4[2]; db = d4[3];
    float m2 = fmaxf(fmaxf(da.x, da.y), fmaxf(da.z, da.w));
    float m3 = fmaxf(fmaxf(db.x, db.y), fmaxf(db.z, db.w));
    float md = fmaxf(fmaxf(m0, m1), fmaxf(m2, m3));

    feat_s[tid][0] = p.x;  feat_s[tid][1] = p.y;  feat_s[tid][2] = p.z;
    feat_s[tid][3] = mnx;  feat_s[tid][4] = mny;  feat_s[tid][5] = mnz;
    feat_s[tid][6] = mdx;  feat_s[tid][7] = mdy;  feat_s[tid][8] = mdz;
    feat_s[tid][9] = md;

    __syncthreads();

    // ---- Phase 2: matvec + relu, coalesced stores ----
    // 16 consecutive lanes cover one point's 64 channels: each warp stores
    // 512B contiguous (4 L1 wavefronts vs 32 for thread-per-point stores).
    int c = tid & 15;          // fixed channel group (256 % 16 == 0)
    int sub = tid >> 4;        // 0..15
    long blk_base = (long)blockIdx.x * TPB;
#pragma unroll
    for (int it = 0; it < 16; it++) {
        int pl = it * 16 + sub;
        float4 acc = Bs[c];
#pragma unroll
        for (int j = 0; j < 10; j++) {
            float f = feat_s[pl][j];   // broadcast LDS
            float4 w = Ws[j][c];       // LDS.128, 2-phase
            acc.x = fmaf(f, w.x, acc.x);
            acc.y = fmaf(f, w.y, acc.y);
            acc.z = fmaf(f, w.z, acc.z);
            acc.w = fmaf(f, w.w, acc.w);
        }
        acc.x = fmaxf(acc.x, 0.0f);
        acc.y = fmaxf(acc.y, 0.0f);
        acc.z = fmaxf(acc.z, 0.0f);
        acc.w = fmaxf(acc.w, 0.0f);
        ((float4*)(out + (blk_base + pl) * HH))[c] = acc;
    }
}

extern "C" void kernel_launch(void* const* d_in, const int* in_sizes, int n_in,
                              void* d_out, int out_size) {
    const float* pos  = (const float*)d_in[0];
    const void*  idx  = d_in[1];
    const float* dist = (const float*)d_in[2];
    const float* W    = (const float*)d_in[3];
    const float* bias = (const float*)d_in[4];
    float* out = (float*)d_out;

    transpose_pos_kernel<<<(BB * NN + TPB - 1) / TPB, TPB>>>(pos, (const unsigned*)idx);
    point_embed_kernel<<<(BB * NN) / TPB, TPB>>>(idx, dist, W, bias, out);
}